// round 4
// baseline (speedup 1.0000x reference)
#include <cuda_runtime.h>

// Problem: N=8192, D=64, H=256
//   h  = tanh(y @ W1 + t*wt + b1)           [N,H]
//   dy = h @ W2 + b2                        [N,D]
//   div_i = sum_j (1 - h_ij^2) * s_j,  s_j = sum_d W1[d,j]*W2[j,d]
//   out = [dy, -div]  -> [N, 65] float32

#define NN 8192
#define DD 64
#define HH 256
#define MT 32            // rows per CTA
#define NT 256           // threads per CTA
#define PITCH (MT + 2)   // 34: even (8B-aligned f32x2) with tolerable conflicts

typedef unsigned long long u64;

__device__ __forceinline__ u64 pack2(float a, float b) {
    u64 r; asm("mov.b64 %0, {%1, %2};" : "=l"(r) : "f"(a), "f"(b)); return r;
}
__device__ __forceinline__ void unpack2(u64 v, float& a, float& b) {
    asm("mov.b64 {%0, %1}, %2;" : "=f"(a), "=f"(b) : "l"(v));
}
// Blackwell packed fp32 FMA (2x FFMA per instruction)
__device__ __forceinline__ u64 fma2(u64 a, u64 b, u64 c) {
    u64 d; asm("fma.rn.f32x2 %0, %1, %2, %3;" : "=l"(d) : "l"(a), "l"(b), "l"(c)); return d;
}
// accurate-enough tanh: correct saturation at +/-inf via __expf/__fdividef
__device__ __forceinline__ float tanh_fast(float x) {
    float e = __expf(2.0f * x);
    return 1.0f - __fdividef(2.0f, e + 1.0f);
}

__global__ void __launch_bounds__(NT) ode_fused(
    const float* __restrict__ tt, const float* __restrict__ y,
    const float* __restrict__ W1, const float* __restrict__ b1,
    const float* __restrict__ wt, const float* __restrict__ W2,
    const float* __restrict__ b2, float* __restrict__ out)
{
    __shared__ float y_s[DD * PITCH];   // transposed y tile: y_s[k][r]
    __shared__ float h_s[HH * PITCH];   // h tile: h_s[j][r]
    __shared__ float c_s[HH];           // t*wt_j + b1_j
    __shared__ float s_s[HH];           // sum_d W1[d,j]*W2[j,d]
    __shared__ float b2_s[DD];
    __shared__ float divp[8 * MT];      // divergence partials

    const int tid  = threadIdx.x;
    const int row0 = blockIdx.x * MT;

    // ---- per-hidden constants (NT == HH: one j per thread) ----
    {
        const int j = tid;
        const float ts = tt[0];
        float c = fmaf(ts, wt[j], b1[j]);
        float s = 0.f;
        #pragma unroll 8
        for (int d = 0; d < DD; d++)
            s = fmaf(W1[d * HH + j], W2[j * DD + d], s);
        c_s[j] = c;
        s_s[j] = s;
        if (tid < DD) b2_s[tid] = b2[tid];
    }

    // ---- load y tile transposed (coalesced float4 reads) ----
    {
        const float4* y4 = (const float4*)(y + (size_t)row0 * DD);
        for (int i = tid; i < MT * DD / 4; i += NT) {
            float4 v = y4[i];
            int r = i >> 4;            // i*4 / 64
            int k = (i & 15) << 2;
            y_s[(k + 0) * PITCH + r] = v.x;
            y_s[(k + 1) * PITCH + r] = v.y;
            y_s[(k + 2) * PITCH + r] = v.z;
            y_s[(k + 3) * PITCH + r] = v.w;
        }
    }
    __syncthreads();

    // ---- Phase A: h = tanh(y@W1 + c) ----
    // thread tile: 8 rows (4 f32x2 pairs) x 4 hidden units
    {
        const int jg = tid & 63, j0 = jg * 4;
        const int rg = tid >> 6, r0 = rg * 8;
        u64 acc[4][4];
        #pragma unroll
        for (int i = 0; i < 4; i++) {
            float c = c_s[j0 + i];
            u64 cc = pack2(c, c);
            #pragma unroll
            for (int p = 0; p < 4; p++) acc[p][i] = cc;
        }
        #pragma unroll 4
        for (int k = 0; k < DD; k++) {
            float4 w = *(const float4*)&W1[k * HH + j0];   // coalesced, L1/L2-hot
            u64 wp0 = pack2(w.x, w.x), wp1 = pack2(w.y, w.y);
            u64 wp2 = pack2(w.z, w.z), wp3 = pack2(w.w, w.w);
            const float* yk = &y_s[k * PITCH + r0];
            #pragma unroll
            for (int p = 0; p < 4; p++) {
                u64 yv = *(const u64*)&yk[2 * p];          // LDS.64 broadcast
                acc[p][0] = fma2(yv, wp0, acc[p][0]);
                acc[p][1] = fma2(yv, wp1, acc[p][1]);
                acc[p][2] = fma2(yv, wp2, acc[p][2]);
                acc[p][3] = fma2(yv, wp3, acc[p][3]);
            }
        }
        #pragma unroll
        for (int i = 0; i < 4; i++) {
            float* hj = &h_s[(j0 + i) * PITCH + r0];
            #pragma unroll
            for (int p = 0; p < 4; p++) {
                float a, b; unpack2(acc[p][i], a, b);
                *(u64*)&hj[2 * p] = pack2(tanh_fast(a), tanh_fast(b));
            }
        }
    }
    __syncthreads();

    // ---- Phase B: dy = h@W2 + b2 ----
    // thread tile: 4 rows (2 f32x2 pairs) x 2 output dims
    {
        const int dg = tid & 31, d0 = dg * 2;
        const int rg = tid >> 5, r0 = rg * 4;
        u64 acc[2][2];
        {
            u64 v0 = pack2(b2_s[d0],     b2_s[d0]);
            u64 v1 = pack2(b2_s[d0 + 1], b2_s[d0 + 1]);
            acc[0][0] = v0; acc[1][0] = v0;
            acc[0][1] = v1; acc[1][1] = v1;
        }
        #pragma unroll 4
        for (int j = 0; j < HH; j++) {
            float2 w = *(const float2*)&W2[j * DD + d0];   // coalesced LDG.64
            u64 wp0 = pack2(w.x, w.x), wp1 = pack2(w.y, w.y);
            const float* hj = &h_s[j * PITCH + r0];
            u64 h0 = *(const u64*)&hj[0];                   // LDS.64 broadcast
            u64 h1 = *(const u64*)&hj[2];
            acc[0][0] = fma2(h0, wp0, acc[0][0]);
            acc[0][1] = fma2(h0, wp1, acc[0][1]);
            acc[1][0] = fma2(h1, wp0, acc[1][0]);
            acc[1][1] = fma2(h1, wp1, acc[1][1]);
        }
        #pragma unroll
        for (int p = 0; p < 2; p++) {
            float a0, b0, a1, b1v;
            unpack2(acc[p][0], a0, b0);
            unpack2(acc[p][1], a1, b1v);
            int r = r0 + 2 * p;
            size_t base0 = (size_t)(row0 + r) * (DD + 1);
            size_t base1 = (size_t)(row0 + r + 1) * (DD + 1);
            out[base0 + d0] = a0; out[base0 + d0 + 1] = a1;
            out[base1 + d0] = b0; out[base1 + d0 + 1] = b1v;
        }
    }

    // ---- divergence: div_r = sum_j (1 - h_rj^2) * s_j ----
    {
        const int r = tid & 31, q = tid >> 5;   // 8 chunks of 32 hidden units
        float g = 0.f;
        #pragma unroll 8
        for (int jj = 0; jj < 32; jj++) {
            int j = q * 32 + jj;
            float h = h_s[j * PITCH + r];       // conflict-free: (2j + r) % 32 distinct in r
            float s = s_s[j];
            g = fmaf(fmaf(-h, h, 1.0f), s, g);
        }
        divp[q * MT + r] = g;
    }
    __syncthreads();
    if (tid < MT) {
        float g = 0.f;
        #pragma unroll
        for (int q = 0; q < 8; q++) g += divp[q * MT + tid];
        out[(size_t)(row0 + tid) * (DD + 1) + DD] = -g;
    }
}

extern "C" void kernel_launch(void* const* d_in, const int* in_sizes, int n_in,
                              void* d_out, int out_size) {
    const float* tt = (const float*)d_in[0];
    const float* y  = (const float*)d_in[1];
    const float* W1 = (const float*)d_in[2];
    const float* b1 = (const float*)d_in[3];
    const float* wt = (const float*)d_in[4];
    const float* W2 = (const float*)d_in[5];
    const float* b2 = (const float*)d_in[6];
    float* out = (float*)d_out;

    ode_fused<<<NN / MT, NT>>>(tt, y, W1, b1, wt, W2, b2, out);
}